// round 14
// baseline (speedup 1.0000x reference)
#include <cuda_runtime.h>

// RotaryEmbedding: x (4,16,8192,64) fp32. Rotate first 4 pairs (elems 0..7)
// of each 64-float row; copy the remaining 56 floats unchanged.
//
// FINAL (R14 = R3 exact revert). Session conclusion:
//   e2e dur = 268MB irreducible DRAM bytes / ~6.15 TB/s sustained mixed-R/W
//   bandwidth ~= 43.5us. Every lever tested:
//   - CHUNKS x TPB sweep {1,4,8,16}x{128,256}: occ*MLP product RF-invariant;
//     optimum = CHUNKS=8/TPB=256 (this config, e2e 43.52 / 43.49 replicated).
//   - Cache hints: full .cs 2x2 matrix + evict_last (modifier AND
//     createpolicy forms) all regress or null — persisting-L2 carveout is 0
//     and its knob is harness-forbidden, so evict_last is a no-op.
//   - TMA bulk staging: identical to LDG path (35.3us hot) — request supply
//     is not the limiter.
//   - Reg caps: spill, never cap. Streaming hints: defeat cross-replay L2.
//   Hot kernel 35.3us (DRAM 76%); hot->e2e gap is trailing writeback drain.

#define CHUNKS 8
#define TPB 256

__device__ __forceinline__ void rope_math(float4 v[CHUNKS], int col4,
                                          const float* __restrict__ dparam,
                                          const float* __restrict__ thetas)
{
    if (col4 < 2) {
        // direction = sigmoid(d)*2 - 1 = tanh(d/2)
        float d = tanhf(0.5f * dparam[0]);
        int p = col4 * 2;
        float s0, c0, s1, c1;
        sincosf(d * thetas[p],     &s0, &c0);
        sincosf(d * thetas[p + 1], &s1, &c1);
        #pragma unroll
        for (int k = 0; k < CHUNKS; k++) {
            float xi0 = v[k].x, xj0 = v[k].y;
            float xi1 = v[k].z, xj1 = v[k].w;
            v[k].x =  xi0 * c0 + xj0 * s0;
            v[k].y = -xi0 * s0 + xj0 * c0;
            v[k].z =  xi1 * c1 + xj1 * s1;
            v[k].w = -xi1 * s1 + xj1 * c1;
        }
    }
}

// Fast path: grid covers n4 exactly, no guards.
__global__ __launch_bounds__(TPB) void rope8_exact(
    const float4* __restrict__ x,
    const float*  __restrict__ dparam,
    const float*  __restrict__ thetas,
    float4*       __restrict__ out)
{
    int base = blockIdx.x * (TPB * CHUNKS) + threadIdx.x;

    float4 v[CHUNKS];
    #pragma unroll
    for (int k = 0; k < CHUNKS; k++)
        v[k] = x[base + k * TPB];

    rope_math(v, base & 15, dparam, thetas);   // TPB=256: col4 invariant

    #pragma unroll
    for (int k = 0; k < CHUNKS; k++)
        out[base + k * TPB] = v[k];
}

// Guarded fallback (not taken for the bench shape).
__global__ __launch_bounds__(TPB) void rope8_guarded(
    const float4* __restrict__ x,
    const float*  __restrict__ dparam,
    const float*  __restrict__ thetas,
    float4*       __restrict__ out,
    int n4)
{
    int base = blockIdx.x * (TPB * CHUNKS) + threadIdx.x;

    float4 v[CHUNKS];
    #pragma unroll
    for (int k = 0; k < CHUNKS; k++) {
        int i = base + k * TPB;
        if (i < n4) v[k] = x[i];
    }

    rope_math(v, base & 15, dparam, thetas);

    #pragma unroll
    for (int k = 0; k < CHUNKS; k++) {
        int i = base + k * TPB;
        if (i < n4) out[i] = v[k];
    }
}

extern "C" void kernel_launch(void* const* d_in, const int* in_sizes, int n_in,
                              void* d_out, int out_size)
{
    const float4* x      = (const float4*)d_in[0];
    const float*  dparam = (const float*)d_in[1];
    const float*  thetas = (const float*)d_in[2];
    float4*       out    = (float4*)d_out;

    int n4 = in_sizes[0] / 4;                   // 8,388,608 float4 chunks
    const int per_block = TPB * CHUNKS;         // 2048
    if (n4 % per_block == 0) {
        rope8_exact<<<n4 / per_block, TPB>>>(x, dparam, thetas, out);
    } else {
        int blocks = (n4 + per_block - 1) / per_block;
        rope8_guarded<<<blocks, TPB>>>(x, dparam, thetas, out, n4);
    }
}

// round 15
// speedup vs baseline: 1.0057x; 1.0057x over previous
#include <cuda_runtime.h>
#include <cstdint>

// RotaryEmbedding: x (4,16,8192,64) fp32. Rotate first 4 pairs (elems 0..7)
// of each 64-float row; copy the remaining 56 floats unchanged.
//
// Evidence (R0-R14): e2e ~= hot + 8.3us (constant gap) -> hot gains transfer
// 1:1. Hot floor so far 35.3us (float4 path == TMA path). Bytes irreducible,
// hints all null/regress, RF caps in-flight bytes, noise +-1.4us.
//
// R15: clean 256-bit LDG/STG (ld/st.global.v8.b32 — exists on sm_103a per
// ptxas diagnostics). R11's 256-bit attempt regressed due to union->local-mem
// codegen (L1 60%); this version keeps all 8 words in scalar regs, no unions.
// Halves memory-instruction count and L1tex wavefronts/byte vs float4.
// CHUNKS=4 x 32B = 128B/thread (R3-optimal in-flight bytes), TPB=256.

#define CHUNKS 4
#define TPB 256

__device__ __forceinline__ void ldg256(const void* p, uint32_t r[8]) {
    asm volatile("ld.global.v8.b32 {%0,%1,%2,%3,%4,%5,%6,%7}, [%8];"
                 : "=r"(r[0]), "=r"(r[1]), "=r"(r[2]), "=r"(r[3]),
                   "=r"(r[4]), "=r"(r[5]), "=r"(r[6]), "=r"(r[7])
                 : "l"(p));
}

__device__ __forceinline__ void stg256(void* p, const uint32_t r[8]) {
    asm volatile("st.global.v8.b32 [%0], {%1,%2,%3,%4,%5,%6,%7,%8};"
                 :: "l"(p),
                    "r"(r[0]), "r"(r[1]), "r"(r[2]), "r"(r[3]),
                    "r"(r[4]), "r"(r[5]), "r"(r[6]), "r"(r[7])
                 : "memory");
}

// Fast path: grid covers n8 exactly, no guards.
__global__ __launch_bounds__(TPB) void rope256_exact(
    const char* __restrict__ x,
    const float* __restrict__ dparam,
    const float* __restrict__ thetas,
    char* __restrict__ out)
{
    int base = blockIdx.x * (TPB * CHUNKS) + threadIdx.x;   // 32B-chunk index

    uint32_t r[CHUNKS][8];
    #pragma unroll
    for (int k = 0; k < CHUNKS; k++)
        ldg256(x + (size_t)(base + k * TPB) * 32, r[k]);

    int col8 = base & 7;                 // TPB=256 == 0 mod 8: invariant
    if (col8 == 0) {
        // direction = sigmoid(d)*2 - 1 = tanh(d/2)
        float d = tanhf(0.5f * dparam[0]);
        float s[4], c[4];
        #pragma unroll
        for (int p = 0; p < 4; p++)
            sincosf(d * thetas[p], &s[p], &c[p]);
        #pragma unroll
        for (int k = 0; k < CHUNKS; k++) {
            #pragma unroll
            for (int p = 0; p < 4; p++) {
                float xi = __int_as_float(r[k][2 * p]);
                float xj = __int_as_float(r[k][2 * p + 1]);
                r[k][2 * p]     = __float_as_int( xi * c[p] + xj * s[p]);
                r[k][2 * p + 1] = __float_as_int(-xi * s[p] + xj * c[p]);
            }
        }
    }

    #pragma unroll
    for (int k = 0; k < CHUNKS; k++)
        stg256(out + (size_t)(base + k * TPB) * 32, r[k]);
}

// Guarded fallback, plain float4 path (not taken for the bench shape).
__global__ __launch_bounds__(TPB) void rope_guarded(
    const float4* __restrict__ x,
    const float*  __restrict__ dparam,
    const float*  __restrict__ thetas,
    float4*       __restrict__ out,
    int n4)
{
    int i = blockIdx.x * TPB + threadIdx.x;
    if (i >= n4) return;
    float4 v = x[i];
    int col4 = i & 15;
    if (col4 < 2) {
        float d = tanhf(0.5f * dparam[0]);
        int p = col4 * 2;
        float s0, c0, s1, c1;
        sincosf(d * thetas[p],     &s0, &c0);
        sincosf(d * thetas[p + 1], &s1, &c1);
        float xi0 = v.x, xj0 = v.y, xi1 = v.z, xj1 = v.w;
        v.x =  xi0 * c0 + xj0 * s0;
        v.y = -xi0 * s0 + xj0 * c0;
        v.z =  xi1 * c1 + xj1 * s1;
        v.w = -xi1 * s1 + xj1 * c1;
    }
    out[i] = v;
}

extern "C" void kernel_launch(void* const* d_in, const int* in_sizes, int n_in,
                              void* d_out, int out_size)
{
    const float* xf     = (const float*)d_in[0];
    const float* dparam = (const float*)d_in[1];
    const float* thetas = (const float*)d_in[2];

    long long nelem = in_sizes[0];
    long long n8 = nelem / 8;                   // 4,194,304 32B chunks
    const int per_block = TPB * CHUNKS;         // 1024
    if (nelem % 8 == 0 && n8 % per_block == 0) {
        rope256_exact<<<(int)(n8 / per_block), TPB>>>(
            (const char*)xf, dparam, thetas, (char*)d_out);
    } else {
        int n4 = (int)(nelem / 4);
        rope_guarded<<<(n4 + TPB - 1) / TPB, TPB>>>(
            (const float4*)xf, dparam, thetas, (float4*)d_out, n4);
    }
}